// round 17
// baseline (speedup 1.0000x reference)
#include <cuda_runtime.h>
#include <cuda_fp16.h>
#include <math_constants.h>
#include <cstdint>

#define BB 8
#define TT 2048
#define CC 1024
#define SS 256
#define KTOP 8
#define CC2LL ((long long)CC * CC)

// ---------------------------------------------------------------------------
// helpers
// ---------------------------------------------------------------------------
__device__ __forceinline__ uint32_t smem_u32(const void* p) {
    uint32_t a;
    asm("{ .reg .u64 t; cvta.to.shared.u64 t, %1; cvt.u32.u64 %0, t; }" : "=r"(a) : "l"(p));
    return a;
}
__device__ __forceinline__ uint32_t pack_h2(float a, float b) {
    __half2 h = __floats2half2_rn(a, b);
    return *reinterpret_cast<uint32_t*>(&h);
}
__device__ __forceinline__ float2 unpack_h2(uint32_t u) {
    __half2 h = *reinterpret_cast<__half2*>(&u);
    return __half22float2(h);
}
__device__ __forceinline__ void mma_f16(float* d, const uint32_t* a, const uint32_t* b) {
    asm volatile(
        "mma.sync.aligned.m16n8k16.row.col.f32.f16.f16.f32 "
        "{%0,%1,%2,%3}, {%4,%5,%6,%7}, {%8,%9}, {%0,%1,%2,%3};"
        : "+f"(d[0]), "+f"(d[1]), "+f"(d[2]), "+f"(d[3])
        : "r"(a[0]), "r"(a[1]), "r"(a[2]), "r"(a[3]), "r"(b[0]), "r"(b[1]));
}
__device__ __forceinline__ void ldsm_x4(uint32_t* r, uint32_t addr) {
    asm volatile("ldmatrix.sync.aligned.m8n8.x4.shared.b16 {%0,%1,%2,%3}, [%4];"
        : "=r"(r[0]), "=r"(r[1]), "=r"(r[2]), "=r"(r[3]) : "r"(addr));
}
__device__ __forceinline__ void ldsm_x2(uint32_t* r, uint32_t addr) {
    asm volatile("ldmatrix.sync.aligned.m8n8.x2.shared.b16 {%0,%1}, [%2];"
        : "=r"(r[0]), "=r"(r[1]) : "r"(addr));
}
__device__ __forceinline__ void cp16(uint32_t saddr, const void* gaddr) {
    asm volatile("cp.async.cg.shared.global [%0], [%1], 16;" :: "r"(saddr), "l"(gaddr));
}
__device__ __forceinline__ uint32_t swz(int row, int u) {
    return (uint32_t)(row * 64 + ((u ^ ((row >> 1) & 3)) << 4));
}

#define WSCALE 32.0f

// ---------------------------------------------------------------------------
// scratch
// ---------------------------------------------------------------------------
__device__ __half g_xh[BB * TT * CC];
__device__ __half g_xl[BB * TT * CC];
__device__ __half g_sh[BB * SS * CC];
__device__ __half g_sl[BB * SS * CC];
__device__ __half g_kqh[BB * SS * CC];
__device__ __half g_kql[BB * SS * CC];
__device__ __half g_pvh[BB * SS * CC];      // pv, fp16
__device__ float  g_scores[BB * TT * SS];
__device__ __half g_wah[2 * CC * CC];       // slot0 = 32*Wq^T, slot1 = 32*Wp
__device__ __half g_wal[2 * CC * CC];
__device__ __half g_wbh[2 * CC * CC];       // slot0 = 32*Wk^T, slot1 = 32*Wv^T
__device__ __half g_wbl[2 * CC * CC];
__device__ __half g_wgh[2 * CC * CC];       // slot0 = G', slot1 = H' (x1024)
__device__ __half g_wgl[2 * CC * CC];

__device__ int g_tick3;
__device__ volatile int g_bar_count;
__device__ volatile int g_bar_sense;

// ---------------------------------------------------------------------------
// grid-wide sense-reversing barrier (all CTAs resident by construction)
// ---------------------------------------------------------------------------
__device__ __forceinline__ void grid_barrier(int nblk) {
    __threadfence();
    __syncthreads();
    if (threadIdx.x == 0) {
        int s = g_bar_sense;
        if (atomicAdd((int*)&g_bar_count, 1) == nblk - 1) {
            g_bar_count = 0;
            __threadfence();
            g_bar_sense = s ^ 1;
        } else {
            while (g_bar_sense == s) __nanosleep(64);
        }
    }
    __syncthreads();
    __threadfence();
}

// ---------------------------------------------------------------------------
// weight prep tile body (t: 0..4095; z = t>>10 selects matrix)
// z=0: Wq^T -> wah s0; z=1: Wk^T -> wbh s0; z=2: Wv^T -> wbh s1; z=3: Wp -> wah s1
// ---------------------------------------------------------------------------
__device__ void wp_body(int t, const float* __restrict__ w0, const float* __restrict__ w1,
                        const float* __restrict__ w2, const float* __restrict__ w3,
                        char* smemraw) {
    const int z = t >> 10, tt = t & 1023;
    const int bx = (tt & 31) * 32, by = (tt >> 5) * 32;
    const int tx = threadIdx.x & 31, ty = threadIdx.x >> 5;

    if (z == 3) {
        __half* oh = g_wah + (size_t)CC * CC;
        __half* ol = g_wal + (size_t)CC * CC;
#pragma unroll
        for (int j = 0; j < 4; j++) {
            size_t o = (size_t)(by + ty * 4 + j) * CC + bx + tx;
            float v = w3[o] * WSCALE;
            __half h = __float2half_rn(v);
            oh[o] = h;
            ol[o] = __float2half_rn(v - __half2float(h));
        }
        return;
    }

    float (*tS)[33] = (float(*)[33])smemraw;
    const float* in = (z == 0) ? w0 : (z == 1) ? w1 : w2;
    __half* oh = (z == 0) ? g_wah : (z == 1) ? g_wbh : (g_wbh + (size_t)CC * CC);
    __half* ol = (z == 0) ? g_wal : (z == 1) ? g_wbl : (g_wbl + (size_t)CC * CC);

    __syncthreads();
#pragma unroll
    for (int j = 0; j < 4; j++)
        tS[ty * 4 + j][tx] = in[(size_t)(by + ty * 4 + j) * CC + bx + tx];
    __syncthreads();
#pragma unroll
    for (int j = 0; j < 4; j++) {
        float v = tS[tx][ty * 4 + j] * WSCALE;
        __half h = __float2half_rn(v);
        size_t o = (size_t)(bx + ty * 4 + j) * CC + by + tx;
        oh[o] = h;
        ol[o] = __float2half_rn(v - __half2float(h));
    }
}

// ---------------------------------------------------------------------------
// pool + x conversion (grid-strided over npool CTAs)
// ---------------------------------------------------------------------------
__device__ void pool_body(int pb, int npool, const float* __restrict__ x) {
    const int stride = npool * 256;
    for (int i = pb * 256 + threadIdx.x; i < BB * SS * CC; i += stride) {
        int c = i & (CC - 1);
        int bs = i >> 10;
        int s = bs & (SS - 1);
        int b = bs >> 8;
        const size_t base = ((size_t)b * TT + (size_t)s * 8) * CC + c;
        float sum = 0.f;
#pragma unroll
        for (int u = 0; u < 8; u++) {
            float v = x[base + (size_t)u * CC];
            sum += v;
            __half h = __float2half_rn(v);
            g_xh[base + (size_t)u * CC] = h;
            g_xl[base + (size_t)u * CC] = __float2half_rn(v - __half2float(h));
        }
        sum *= 0.125f;
        __half h = __float2half_rn(sum);
        g_sh[i] = h;
        g_sl[i] = __float2half_rn(sum - __half2float(h));
    }
}

// ---------------------------------------------------------------------------
// R12/R16-proven split-fp16 HMMA GEMM core. CTA 128x128, BK=32, 8 warps,
// warp tile 64x32; 2-stage cp.async. emode: 0 fp32, 1 fp16 hi/lo, 3 fp16 hi.
// ---------------------------------------------------------------------------
#define STAGES 2
#define STAGE_BYTES 32768
#define GEMM_SMEM (STAGES * STAGE_BYTES)

__device__ void gemm_core(
    const __half* __restrict__ gAh, const __half* __restrict__ gAl,
    const __half* __restrict__ gBh, const __half* __restrict__ gBl,
    float* __restrict__ Cf, __half* __restrict__ Chi, __half* __restrict__ Clo,
    int N, int K, size_t m0, size_t n0,
    float a, int emode, bool full3, uint32_t sb) {

    const int tid = threadIdx.x;
    const int wid = tid >> 5;
    const int lane = tid & 31;

    const int lrow = tid >> 1;
    const int lu   = (tid & 1) * 2;
    const size_t aoffg = (m0 + lrow) * (size_t)K;
    const size_t boffg = (n0 + lrow) * (size_t)K;

    const int nch = K >> 5;

#define LOAD_STAGE(stg) do { \
    const uint32_t st = sb + ((stg) % STAGES) * STAGE_BYTES; \
    const int kof = (stg) * 32; \
    _Pragma("unroll") \
    for (int j = 0; j < 2; j++) { \
        int u = lu + j; \
        uint32_t so = swz(lrow, u); \
        size_t goa = aoffg + kof + u * 8; \
        size_t gob = boffg + kof + u * 8; \
        cp16(st + so,         gAh + goa); \
        cp16(st + 8192 + so,  gAl + goa); \
        cp16(st + 16384 + so, gBh + gob); \
        cp16(st + 24576 + so, gBl + gob); \
    } \
} while (0)

    const int wm = wid >> 2;
    const int wn = wid & 3;

    float acc[4][4][4];
#pragma unroll
    for (int i = 0; i < 4; i++)
#pragma unroll
        for (int j = 0; j < 4; j++)
#pragma unroll
            for (int r = 0; r < 4; r++) acc[i][j][r] = 0.f;

    LOAD_STAGE(0);
    asm volatile("cp.async.commit_group;" ::: "memory");

    for (int c = 0; c < nch; c++) {
        asm volatile("cp.async.wait_group 0;" ::: "memory");
        __syncthreads();

        if (c + 1 < nch) LOAD_STAGE(c + 1);
        asm volatile("cp.async.commit_group;" ::: "memory");

        const uint32_t st = sb + (c % STAGES) * STAGE_BYTES;
#pragma unroll
        for (int ks = 0; ks < 2; ks++) {
            uint32_t bhf[4][2], blf[4][2];
            const int rB0 = wn * 32 + (lane & 7);
            const int cuB = 2 * ks + ((lane >> 3) & 1);
#pragma unroll
            for (int fn = 0; fn < 4; fn++) {
                uint32_t ad = st + 16384 + swz(rB0 + 8 * fn, cuB);
                ldsm_x2(bhf[fn], ad);
                ldsm_x2(blf[fn], ad + 8192);
            }
#pragma unroll
            for (int fm = 0; fm < 4; fm++) {
                int rowA = wm * 64 + fm * 16 + (lane & 7) + ((lane >> 3) & 1) * 8;
                int cuA = 2 * ks + (lane >> 4);
                uint32_t ad = st + swz(rowA, cuA);
                uint32_t ah[4], al[4];
                ldsm_x4(ah, ad);
                ldsm_x4(al, ad + 8192);
#pragma unroll
                for (int fn = 0; fn < 4; fn++) mma_f16(acc[fm][fn], ah, bhf[fn]);
                if (full3) {
#pragma unroll
                    for (int fn = 0; fn < 4; fn++) mma_f16(acc[fm][fn], ah, blf[fn]);
                }
#pragma unroll
                for (int fn = 0; fn < 4; fn++) mma_f16(acc[fm][fn], al, bhf[fn]);
            }
        }
    }
#undef LOAD_STAGE

    const int eg = lane >> 2;
    const int et = lane & 3;

#pragma unroll
    for (int fm = 0; fm < 4; fm++) {
        size_t row0 = m0 + wm * 64 + fm * 16 + eg;
#pragma unroll
        for (int fn = 0; fn < 4; fn++) {
            size_t col = n0 + wn * 32 + fn * 8 + et * 2;
            float c0 = a * acc[fm][fn][0];
            float c1 = a * acc[fm][fn][1];
            float c2 = a * acc[fm][fn][2];
            float c3 = a * acc[fm][fn][3];
            if (emode == 0) {
                *(float2*)(Cf + row0 * N + col)       = make_float2(c0, c1);
                *(float2*)(Cf + (row0 + 8) * N + col) = make_float2(c2, c3);
            } else if (emode == 3) {
                *(uint32_t*)(Chi + row0 * N + col)       = pack_h2(c0, c1);
                *(uint32_t*)(Chi + (row0 + 8) * N + col) = pack_h2(c2, c3);
            } else {
                uint32_t h0 = pack_h2(c0, c1);
                float2 e0 = unpack_h2(h0);
                uint32_t l0 = pack_h2(c0 - e0.x, c1 - e0.y);
                uint32_t h1 = pack_h2(c2, c3);
                float2 e1 = unpack_h2(h1);
                uint32_t l1 = pack_h2(c2 - e1.x, c3 - e1.y);
                *(uint32_t*)(Chi + row0 * N + col)       = h0;
                *(uint32_t*)(Clo + row0 * N + col)       = l0;
                *(uint32_t*)(Chi + (row0 + 8) * N + col) = h1;
                *(uint32_t*)(Clo + (row0 + 8) * N + col) = l1;
            }
        }
    }
}

// ---------------------------------------------------------------------------
// topk body: block-task t handles 8 rows (one per warp); gathers fp16 pv
// ---------------------------------------------------------------------------
__device__ void topk_body(int tsk, float* __restrict__ out) {
    const int wid = threadIdx.x >> 5;
    const int lane = threadIdx.x & 31;
    const int warp_global = tsk * 8 + wid;      // b*T + t
    const int b = warp_global >> 11;
    const int t = warp_global & (TT - 1);

    const float* srow = g_scores + ((long)b * TT + t) * SS;

    float vals[8];
#pragma unroll
    for (int i = 0; i < 8; i++) vals[i] = srow[lane + 32 * i];

    float w[KTOP];
    int   idx[KTOP];

#pragma unroll
    for (int r = 0; r < KTOP; r++) {
        float best = -CUDART_INF_F;
        int   bi = 0x7fffffff;
#pragma unroll
        for (int i = 0; i < 8; i++)
            if (vals[i] > best) { best = vals[i]; bi = lane + 32 * i; }
#pragma unroll
        for (int off = 16; off; off >>= 1) {
            float ov = __shfl_xor_sync(0xffffffffu, best, off);
            int   oi = __shfl_xor_sync(0xffffffffu, bi, off);
            if (ov > best || (ov == best && oi < bi)) { best = ov; bi = oi; }
        }
        w[r] = best;
        idx[r] = bi;
#pragma unroll
        for (int i = 0; i < 8; i++)
            if ((lane + 32 * i) == bi) vals[i] = -CUDART_INF_F;
    }

    float mx = w[0];
    float sum = 0.f;
#pragma unroll
    for (int r = 0; r < KTOP; r++) { w[r] = __expf(w[r] - mx); sum += w[r]; }
    float inv = 0.5f / sum;
#pragma unroll
    for (int r = 0; r < KTOP; r++) w[r] *= inv;

    const __half* pvb = g_pvh + (long)b * SS * CC;
    float* o = out + ((long)b * TT + t) * CC;
#pragma unroll
    for (int it = 0; it < CC / 128; it++) {
        int c = lane * 4 + it * 128;
        float4 acc = make_float4(0.f, 0.f, 0.f, 0.f);
#pragma unroll
        for (int r = 0; r < KTOP; r++) {
            uint2 raw = *(const uint2*)(pvb + (long)idx[r] * CC + c);
            float2 f0 = unpack_h2(raw.x);
            float2 f1 = unpack_h2(raw.y);
            acc.x = fmaf(w[r], f0.x, acc.x);
            acc.y = fmaf(w[r], f0.y, acc.y);
            acc.z = fmaf(w[r], f1.x, acc.z);
            acc.w = fmaf(w[r], f1.y, acc.w);
        }
        *(float4*)(o + c) = acc;
    }
}

// ---------------------------------------------------------------------------
// persistent kernel: P0 wp | P1 G'/H' + pool | P2 kq | P3 scores + pv | P4 topk
// ---------------------------------------------------------------------------
__global__ __launch_bounds__(256, 2)
void persist(const float* __restrict__ x, const float* __restrict__ Wq,
             const float* __restrict__ Wk, const float* __restrict__ Wv,
             const float* __restrict__ Wp, float* __restrict__ out, int nblk) {
    extern __shared__ __align__(16) char smem[];
    const uint32_t sb = smem_u32(smem);
    const int bid = blockIdx.x;
    __shared__ int s_t;

    // P0: weight prep
    for (int t = bid; t < 4096; t += nblk) wp_body(t, Wq, Wk, Wv, Wp, smem);
    grid_barrier(nblk);

    // P1..P3: GEMM phases (single gemm_core call site)
    for (int ph = 1; ph <= 3; ph++) {
        if (ph == 1 && bid >= 128) pool_body(bid - 128, nblk - 128, x);

        const int ntask = (ph == 3) ? 384 : 128;
        int t;
        if (ph == 3) {
            if (threadIdx.x == 0) s_t = atomicAdd(&g_tick3, 1);
            __syncthreads();
            t = s_t;
        } else {
            t = (bid < 128) ? bid : ntask;
        }

        while (t < ntask) {
            const __half *Ah, *Al, *Bh, *Bl;
            __half *Chi = nullptr, *Clo = nullptr;
            float* Cf = nullptr;
            int N, emode, m0t, n0t;
            float alpha;
            bool full3;

            if (ph == 1) {
                int z2 = t >> 6, tt = t & 63;
                size_t off = (size_t)z2 * (size_t)CC * CC;
                Ah = g_wah + off; Al = g_wal + off;
                Bh = g_wbh + off; Bl = g_wbl + off;
                Chi = g_wgh + off; Clo = g_wgl + off;
                N = CC; emode = 1; alpha = 1.0f; full3 = (z2 == 0);
                m0t = tt >> 3; n0t = tt & 7;
            } else if (ph == 2) {
                Ah = g_sh; Al = g_sl; Bh = g_wgh; Bl = g_wgl;
                Chi = g_kqh; Clo = g_kql;
                N = CC; emode = 1; alpha = 1.0f; full3 = true;
                m0t = t >> 3; n0t = t & 7;
            } else if (t < 256) {
                int b = t >> 5, tt = t & 31;
                Ah = g_xh + (size_t)b * TT * CC; Al = g_xl + (size_t)b * TT * CC;
                Bh = g_kqh + (size_t)b * SS * CC; Bl = g_kql + (size_t)b * SS * CC;
                Cf = g_scores + (size_t)b * TT * SS;
                N = SS; emode = 0; alpha = 1.0f / 32768.0f; full3 = true;
                m0t = tt >> 1; n0t = tt & 1;
            } else {
                int tt = t - 256;
                Ah = g_sh; Al = g_sl;
                Bh = g_wgh + (size_t)CC * CC; Bl = g_wgl + (size_t)CC * CC;
                Chi = g_pvh;
                N = CC; emode = 3; alpha = 1.0f / 1024.0f; full3 = false;
                m0t = tt >> 3; n0t = tt & 7;
            }

            gemm_core(Ah, Al, Bh, Bl, Cf, Chi, Clo, N, CC,
                      (size_t)m0t * 128, (size_t)n0t * 128,
                      alpha, emode, full3, sb);

            if (ph == 3) {
                __syncthreads();
                if (threadIdx.x == 0) s_t = atomicAdd(&g_tick3, 1);
                __syncthreads();
                t = s_t;
            } else {
                t = ntask;
            }
        }
        grid_barrier(nblk);
        if (ph == 3 && bid == 0 && threadIdx.x == 0) g_tick3 = 0;
    }

    // P4: topk + gather
    for (int t = bid; t < (BB * TT) / 8; t += nblk) topk_body(t, out);
}

// ---------------------------------------------------------------------------
// launch
// ---------------------------------------------------------------------------
extern "C" void kernel_launch(void* const* d_in, const int* in_sizes, int n_in,
                              void* d_out, int out_size) {
    const float* x  = (const float*)d_in[0];
    const float* Wq = (const float*)d_in[1];
    const float* Wk = (const float*)d_in[2];
    const float* Wv = (const float*)d_in[3];
    const float* Wp = (const float*)d_in[4];
    float* out = (float*)d_out;

    cudaFuncSetAttribute(persist, cudaFuncAttributeMaxDynamicSharedMemorySize, GEMM_SMEM);

    int dev = 0;
    cudaGetDevice(&dev);
    int nsm = 148;
    cudaDeviceGetAttribute(&nsm, cudaDevAttrMultiProcessorCount, dev);
    int perSM = 0;
    cudaOccupancyMaxActiveBlocksPerMultiprocessor(&perSM, persist, 256, GEMM_SMEM);
    if (perSM < 1) perSM = 1;
    int grid = nsm * perSM;

    persist<<<grid, 256, GEMM_SMEM>>>(x, Wq, Wk, Wv, Wp, out, grid);
}